// round 5
// baseline (speedup 1.0000x reference)
#include <cuda_runtime.h>
#include <cuda_bf16.h>
#include <cuda_fp8.h>
#include <cstdint>

// ---------------- problem constants ----------------
#define NPRED 1200
#define NTGT  256
#define NCLS  80
#define HW    128
#define SRC   256
#define PIX   16384
#define KTOT  16384     // K in elements (== bytes for e4m3)
#define MROWS 2400      // rows 0..1199: X (logits), 1200..2399: sigmoid(X)

// ---------------- GEMM config (legacy mma.sync fp8, sm_100-safe) ----------------
#define BM     128
#define BN     256
#define BKB    128                // k-tile depth in BYTES (=128 e4m3 elements)
#define NKT    (KTOT / BKB)       // 128 k-tiles total
#define SPLITK 7
#define MT     19                 // ceil(2400/128)
#define STAGES 3
#define ABYTES (BM * 128)         // 16 KB
#define BBYTES (BN * 128)         // 32 KB
#define STGB   (ABYTES + BBYTES)  // 48 KB
#define SMEMSZ (1024 + STAGES * STGB)

// ---------------- scratch (device globals; no allocs) ----------------
__device__ __align__(16) uint8_t g_Ab[(size_t)MROWS * KTOT];        // 39.3 MB e4m3
__device__ __align__(16) uint8_t g_Tb[(size_t)NTGT * KTOT];         //  4.2 MB e4m3
__device__ __align__(16) float g_D[SPLITK][(size_t)MROWS * NTGT];   // 17.2 MB
__device__ float g_tsum4[NTGT * 4];
__device__ float g_ssum[NPRED];
__device__ float g_sigsum[NPRED];

// ---------------- PTX helpers ----------------
__device__ __forceinline__ uint32_t smem_u32(const void* p) {
    uint32_t a;
    asm("{ .reg .u64 t; cvta.to.shared.u64 t, %1; cvt.u32.u64 %0, t; }" : "=r"(a) : "l"(p));
    return a;
}
__device__ __forceinline__ void cp16(uint32_t sdst, const void* src, int nbytes) {
    asm volatile("cp.async.cg.shared.global [%0], [%1], 16, %2;\n"
                 ::"r"(sdst), "l"(src), "r"(nbytes));
}
__device__ __forceinline__ void ldsm4(uint32_t* r, uint32_t addr) {
    asm volatile("ldmatrix.sync.aligned.m8n8.x4.shared.b16 {%0,%1,%2,%3}, [%4];"
                 : "=r"(r[0]), "=r"(r[1]), "=r"(r[2]), "=r"(r[3]) : "r"(addr));
}
__device__ __forceinline__ void mma_fp8(float* d, const uint32_t* a, const uint32_t* b) {
    asm volatile(
        "mma.sync.aligned.m16n8k32.row.col.f32.e4m3.e4m3.f32 "
        "{%0,%1,%2,%3}, {%4,%5,%6,%7}, {%8,%9}, {%0,%1,%2,%3};\n"
        : "+f"(d[0]), "+f"(d[1]), "+f"(d[2]), "+f"(d[3])
        : "r"(a[0]), "r"(a[1]), "r"(a[2]), "r"(a[3]), "r"(b[0]), "r"(b[1]));
}

__device__ __forceinline__ uint32_t pack4_e4m3(float a, float b, float c, float d) {
    __nv_fp8x2_storage_t lo =
        __nv_cvt_float2_to_fp8x2(make_float2(a, b), __NV_SATFINITE, __NV_E4M3);
    __nv_fp8x2_storage_t hi =
        __nv_cvt_float2_to_fp8x2(make_float2(c, d), __NV_SATFINITE, __NV_E4M3);
    return (uint32_t)lo | ((uint32_t)hi << 16);
}

template <int NW>
__device__ __forceinline__ float block_sum(float v) {
    __shared__ float red[NW];
    int lane = threadIdx.x & 31, w = threadIdx.x >> 5;
#pragma unroll
    for (int o = 16; o > 0; o >>= 1) v += __shfl_down_sync(0xffffffffu, v, o);
    if (lane == 0) red[w] = v;
    __syncthreads();
    if (w == 0) {
        v = (lane < NW) ? red[lane] : 0.f;
#pragma unroll
        for (int o = NW / 2; o > 0; o >>= 1) v += __shfl_down_sync(0xffffffffu, v, o);
    }
    return v;  // valid on thread 0
}

// jax.image.resize(antialias=True) 2x-down triangle taps, edge-renormalized.
__device__ __forceinline__ void make_taps(int i, int* j, float* w) {
    const float bw[4] = {0.125f, 0.375f, 0.375f, 0.125f};
    float s = 0.f;
#pragma unroll
    for (int d = 0; d < 4; ++d) {
        int jj = 2 * i - 1 + d;
        bool ok = (jj >= 0) && (jj < SRC);
        j[d] = ok ? jj : 0;
        w[d] = ok ? bw[d] : 0.f;
        s += w[d];
    }
    float inv = 1.f / s;
#pragma unroll
    for (int d = 0; d < 4; ++d) w[d] *= inv;
}

// ---------------- kernel 1: resize targets 256x256 -> 128x128 (e4m3) + tsum ----------------
__global__ __launch_bounds__(128) void k_resize(const float* __restrict__ tgt) {
    int m = blockIdx.x;
    int chunk = blockIdx.y;   // 4 row-chunks of 32
    int x = threadIdx.x;
    const float* src = tgt + (size_t)m * (SRC * SRC);
    uint8_t* dst = g_Tb + (size_t)m * PIX;

    int jx[4]; float wx[4];
    make_taps(x, jx, wx);

    float sum = 0.f;
    int y0 = chunk * 32;
    for (int y = y0; y < y0 + 32; ++y) {
        int jy[4]; float wy[4];
        make_taps(y, jy, wy);
        float v = 0.f;
#pragma unroll
        for (int dy = 0; dy < 4; ++dy) {
            const float* row = src + (size_t)jy[dy] * SRC;
            float h = wx[0] * row[jx[0]] + wx[1] * row[jx[1]] +
                      wx[2] * row[jx[2]] + wx[3] * row[jx[3]];
            v += wy[dy] * h;
        }
        dst[y * HW + x] = (uint8_t)__nv_cvt_float_to_fp8(v, __NV_SATFINITE, __NV_E4M3);
        sum += v;
    }
    float tot = block_sum<4>(sum);
    if (threadIdx.x == 0) g_tsum4[m * 4 + chunk] = tot;
}

// ---------------- kernel 2: pred_masks -> e4m3 X & sigmoid(X); rowsums ----------------
__global__ __launch_bounds__(256) void k_convert(const float* __restrict__ pm) {
    int n = blockIdx.x;
    const float4* src = (const float4*)(pm + (size_t)n * PIX);
    uint32_t* dx = (uint32_t*)(g_Ab + (size_t)n * KTOT);
    uint32_t* ds = (uint32_t*)(g_Ab + (size_t)(NPRED + n) * KTOT);

    float ssum = 0.f, gsum = 0.f;
    for (int i = threadIdx.x; i < PIX / 4; i += 256) {
        float4 v = src[i];
        float xs[4] = {v.x, v.y, v.z, v.w};
        float sg[4];
#pragma unroll
        for (int c = 0; c < 4; ++c) {
            float xv = xs[c];
            sg[c] = 1.f / (1.f + __expf(-xv));
            gsum += sg[c];
            ssum += fmaxf(xv, 0.f) + log1pf(__expf(-fabsf(xv)));  // softplus
        }
        dx[i] = pack4_e4m3(xs[0], xs[1], xs[2], xs[3]);
        ds[i] = pack4_e4m3(sg[0], sg[1], sg[2], sg[3]);
    }
    float s_tot = block_sum<8>(ssum);
    __syncthreads();
    float g_tot = block_sum<8>(gsum);
    if (threadIdx.x == 0) {
        g_ssum[n] = s_tot;
        g_sigsum[n] = g_tot;
    }
}

// ---------------- kernel 3: fp8 GEMM  D[kz] = A(128 x K) @ T^T(256 x K) ----------------
__global__ __launch_bounds__(256, 1) void k_gemm() {
    extern __shared__ char smem[];
    const uint32_t tiles = (smem_u32(smem) + 1023u) & ~1023u;

    const int tid = threadIdx.x;
    const int lane = tid & 31;
    const int wid = tid >> 5;
    const int wm = wid & 1;    // 2 warp-rows of 64
    const int wn = wid >> 1;   // 4 warp-cols of 64
    const int m0 = blockIdx.x * BM;
    const int kz = blockIdx.y;
    // balanced split-K tile partition
    const int t0 = (kz * NKT) / SPLITK;
    const int t1 = ((kz + 1) * NKT) / SPLITK;
    const int NT = t1 - t0;           // 18 or 19
    const int kbase = t0 * BKB;       // byte offset into K

    auto load_tile = [&](int j) {
        int stage = j % STAGES;
        uint32_t ab = tiles + stage * STGB;
        uint32_t bb = ab + ABYTES;
        int k0 = kbase + j * BKB;
        // A: 128 rows x 128B = 1024 chunks of 16B
#pragma unroll
        for (int i = 0; i < 4; ++i) {
            int idx = tid + (i << 8);
            int row = idx >> 3, c16 = idx & 7;
            int grow = m0 + row;
            const void* src = g_Ab + (size_t)(grow < MROWS ? grow : 0) * KTOT + k0 + c16 * 16;
            uint32_t off = (uint32_t)(row * 128 + ((c16 * 16) ^ ((row & 7) << 4)));
            cp16(ab + off, src, grow < MROWS ? 16 : 0);
        }
        // B: 256 rows x 128B = 2048 chunks of 16B
#pragma unroll
        for (int i = 0; i < 8; ++i) {
            int idx = tid + (i << 8);
            int row = idx >> 3, c16 = idx & 7;
            const void* src = g_Tb + (size_t)row * KTOT + k0 + c16 * 16;
            uint32_t off = (uint32_t)(row * 128 + ((c16 * 16) ^ ((row & 7) << 4)));
            cp16(bb + off, src, 16);
        }
        asm volatile("cp.async.commit_group;\n" ::: "memory");
    };

    // per-thread ldmatrix bases (byte-layout identical to bf16 16816 case)
    const int arow = wm * 64 + (lane & 7) + (lane & 8);
    const uint32_t acol0 = (uint32_t)(((lane >> 4) & 1) * 16);
    const int brow0 = wn * 64 + (lane & 7) + ((lane >> 1) & 8);
    const uint32_t bcol0 = (uint32_t)((lane & 8) * 2);

    float acc[4][8][4];
#pragma unroll
    for (int a = 0; a < 4; ++a)
#pragma unroll
        for (int b = 0; b < 8; ++b)
#pragma unroll
            for (int c = 0; c < 4; ++c) acc[a][b][c] = 0.f;

    load_tile(0);
    load_tile(1);

#pragma unroll 1
    for (int kt = 0; kt < NT; ++kt) {
        if (kt + 2 < NT) {
            load_tile(kt + 2);
            asm volatile("cp.async.wait_group 2;\n" ::: "memory");
        } else if (kt + 1 < NT) {
            asm volatile("cp.async.wait_group 1;\n" ::: "memory");
        } else {
            asm volatile("cp.async.wait_group 0;\n" ::: "memory");
        }
        __syncthreads();

        int stage = kt % STAGES;
        uint32_t ab = tiles + stage * STGB;
        uint32_t bb = ab + ABYTES;

#pragma unroll
        for (int kb = 0; kb < 4; ++kb) {   // each kb = 32 bytes = K=32 e4m3
            uint32_t af[4][4], bf[8][2];
            uint32_t acolb = (uint32_t)(kb * 32) + acol0;
            uint32_t bcolb = (uint32_t)(kb * 32) + bcol0;
#pragma unroll
            for (int mb = 0; mb < 4; ++mb) {
                int r = arow + mb * 16;
                ldsm4(af[mb], ab + (uint32_t)(r * 128) + (acolb ^ ((uint32_t)(r & 7) << 4)));
            }
#pragma unroll
            for (int p = 0; p < 4; ++p) {
                int r = brow0 + p * 16;
                uint32_t tmp[4];
                ldsm4(tmp, bb + (uint32_t)(r * 128) + (bcolb ^ ((uint32_t)(r & 7) << 4)));
                bf[2 * p][0] = tmp[0]; bf[2 * p][1] = tmp[1];
                bf[2 * p + 1][0] = tmp[2]; bf[2 * p + 1][1] = tmp[3];
            }
#pragma unroll
            for (int mb = 0; mb < 4; ++mb)
#pragma unroll
                for (int nb = 0; nb < 8; ++nb) mma_fp8(acc[mb][nb], af[mb], bf[nb]);
        }
        __syncthreads();
    }

    // epilogue
    float* Dp = g_D[kz];
    const int trow = lane >> 2;
    const int tcol = (lane & 3) * 2;
#pragma unroll
    for (int mb = 0; mb < 4; ++mb) {
        int r0 = m0 + wm * 64 + mb * 16 + trow;
        int r1 = r0 + 8;
#pragma unroll
        for (int nb = 0; nb < 8; ++nb) {
            int col = wn * 64 + nb * 8 + tcol;
            if (r0 < MROWS)
                *(float2*)&Dp[(size_t)r0 * NTGT + col] = make_float2(acc[mb][nb][0], acc[mb][nb][1]);
            if (r1 < MROWS)
                *(float2*)&Dp[(size_t)r1 * NTGT + col] = make_float2(acc[mb][nb][2], acc[mb][nb][3]);
        }
    }
}

// ---------------- kernel 4: assemble final cost matrix ----------------
__global__ __launch_bounds__(256) void k_assemble(const float* __restrict__ logits,
                                                  const float* __restrict__ pboxes,
                                                  const int* __restrict__ ids,
                                                  const float* __restrict__ tboxes,
                                                  float* __restrict__ out) {
    int n = blockIdx.x;
    int m = threadIdx.x;

    float4 pb = ((const float4*)pboxes)[n];
    float4 tb = ((const float4*)tboxes)[m];

    float cbbox = fabsf(pb.x - tb.x) + fabsf(pb.y - tb.y) +
                  fabsf(pb.z - tb.z) + fabsf(pb.w - tb.w);

    float p1x = pb.x - 0.5f * pb.z, p1y = pb.y - 0.5f * pb.w;
    float p2x = pb.x + 0.5f * pb.z, p2y = pb.y + 0.5f * pb.w;
    float t1x = tb.x - 0.5f * tb.z, t1y = tb.y - 0.5f * tb.w;
    float t2x = tb.x + 0.5f * tb.z, t2y = tb.y + 0.5f * tb.w;
    float area1 = (p2x - p1x) * (p2y - p1y);
    float area2 = (t2x - t1x) * (t2y - t1y);
    float iw = fmaxf(fminf(p2x, t2x) - fmaxf(p1x, t1x), 0.f);
    float ih = fmaxf(fminf(p2y, t2y) - fmaxf(p1y, t1y), 0.f);
    float inter = iw * ih;
    float uni = area1 + area2 - inter;
    float iou = inter / uni;
    float ew = fmaxf(fmaxf(p2x, t2x) - fminf(p1x, t1x), 0.f);
    float eh = fmaxf(fmaxf(p2y, t2y) - fminf(p1y, t1y), 0.f);
    float ae = ew * eh;
    float cgiou = -(iou - (ae - uni) / ae);

    int id = ids[m];
    float lg = logits[(size_t)n * NCLS + id];
    float cclass = -1.f / (1.f + expf(-lg));

    size_t ix = (size_t)n * NTGT + m;
    size_t is = (size_t)(NPRED + n) * NTGT + m;
    float dX = 0.f, dS = 0.f;
#pragma unroll
    for (int s = 0; s < SPLITK; ++s) {
        dX += g_D[s][ix];
        dS += g_D[s][is];
    }

    float tsum = g_tsum4[m * 4] + g_tsum4[m * 4 + 1] + g_tsum4[m * 4 + 2] + g_tsum4[m * 4 + 3];
    float cmask = (g_ssum[n] - dX) * (1.f / (float)PIX);
    float denom = fmaxf(g_sigsum[n] + tsum, 1e-6f) + 1.f;
    float cdice = -(2.f * dS + 1.f) / denom;

    out[ix] = 5.f * cbbox + 2.f * cgiou + 2.f * cclass + 2.f * cmask + 2.f * cdice;
}

// ---------------- launch ----------------
extern "C" void kernel_launch(void* const* d_in, const int* in_sizes, int n_in,
                              void* d_out, int out_size) {
    const float* logits = (const float*)d_in[0];
    const float* pboxes = (const float*)d_in[1];
    const float* pmasks = (const float*)d_in[2];
    const int*   ids    = (const int*)d_in[3];
    const float* tboxes = (const float*)d_in[4];
    const float* tmasks = (const float*)d_in[5];
    float* out = (float*)d_out;

    cudaFuncSetAttribute(k_gemm, cudaFuncAttributeMaxDynamicSharedMemorySize, SMEMSZ);

    k_resize<<<dim3(NTGT, 4), 128>>>(tmasks);
    k_convert<<<NPRED, 256>>>(pmasks);
    k_gemm<<<dim3(MT, SPLITK), 256, SMEMSZ>>>();
    k_assemble<<<NPRED, NTGT>>>(logits, pboxes, ids, tboxes, out);
}